// round 3
// baseline (speedup 1.0000x reference)
#include <cuda_runtime.h>
#include <cuda_bf16.h>
#include <cstdint>

// ---------------------------------------------------------------------------
// GCNEncoder: 2-layer GCN, N=100000 nodes, E=3200000 edges, 128 -> 32 -> 16.
//
// Math factorization: norm = dinv[row]*dinv[col] separates, so
//   layer(x) = dinv ⊙ ( A^T (dinv ⊙ (x W)) ) + b
// Per edge we only gather one pre-scaled feature row and scatter-add it.
// g1 (12.8MB) and g2 (6.4MB) are L2-resident on GB300 (126MB L2), so the
// scatter phase is L2-atomic bound, not HBM bound. We use red.global.add.v4.f32
// to quarter the RED instruction count.
// ---------------------------------------------------------------------------

#define N_NODES 100000
#define N_EDGES 3200000
#define IN_C    128
#define HID     32
#define OUT_C   16

// Scratch (no cudaMalloc allowed) ------------------------------------------
__device__ float g_deg [N_NODES];
__device__ float g_dinv[N_NODES];
__device__ float g_g1  [N_NODES * HID];    // dinv ⊙ (x @ W1)
__device__ float g_acc1[N_NODES * HID];    // scatter accumulator, layer 1
__device__ float g_g2  [N_NODES * OUT_C];  // dinv ⊙ (relu(...) @ W2)
__device__ float g_acc2[N_NODES * OUT_C];  // scatter accumulator, layer 2
__device__ int   g_is64;                   // edge_index dtype flag

// edge_index accessors: layout is [2, E]; row = [0:E), col = [E:2E).
__device__ __forceinline__ int edge_row(const void* ei, int e, int is64) {
    return is64 ? (int)((const long long*)ei)[e] : ((const int*)ei)[e];
}
__device__ __forceinline__ int edge_col(const void* ei, int e, int is64) {
    return is64 ? (int)((const long long*)ei)[(size_t)N_EDGES + e]
                : ((const int*)ei)[(size_t)N_EDGES + e];
}

// ---------------------------------------------------------------------------
// K0: dtype detection. If the data is really int32, an int64 read combines two
// random values in [0,1e5): v = lo + hi*2^32 >= 2^32 unless hi==0 (p=1e-5).
// Over 2048 samples, misdetection probability ~0. Deterministic every call.
// ---------------------------------------------------------------------------
__global__ void k_detect(const void* __restrict__ ei) {
    __shared__ int bad;
    if (threadIdx.x == 0) bad = 0;
    __syncthreads();
    const long long* p = (const long long*)ei;
    for (int i = threadIdx.x; i < 2048; i += blockDim.x) {
        long long v = p[i];
        if (v < 0 || v >= N_NODES) atomicOr(&bad, 1);
    }
    __syncthreads();
    if (threadIdx.x == 0) g_is64 = (bad == 0) ? 1 : 0;
}

// K1: degree of each target node (edge weight 1).
__global__ void k_deg(const void* __restrict__ ei) {
    int t = blockIdx.x * blockDim.x + threadIdx.x;
    if (t >= N_EDGES) return;
    int is64 = g_is64;
    atomicAdd(&g_deg[edge_col(ei, t, is64)], 1.0f);
}

// K2: dinv = deg>0 ? rsqrt(deg) : 0
__global__ void k_dinv() {
    int t = blockIdx.x * blockDim.x + threadIdx.x;
    if (t >= N_NODES) return;
    float d = g_deg[t];
    g_dinv[t] = (d > 0.0f) ? rsqrtf(d) : 0.0f;
}

// K3: g1[i][:] = dinv[i] * (x[i] @ W1).  One warp per node, lane = out feature.
// W1 (128x32 = 16KB) in smem; x row staged in smem per warp (broadcast LDS).
__global__ __launch_bounds__(256) void k_gemm1(const float* __restrict__ x,
                                               const float* __restrict__ W1) {
    __shared__ float sW[IN_C * HID];
    __shared__ float sx[8][IN_C];
    for (int i = threadIdx.x; i < IN_C * HID; i += 256) sW[i] = W1[i];
    __syncthreads();

    int warp = threadIdx.x >> 5, lane = threadIdx.x & 31;
    int node = blockIdx.x * 8 + warp;
    if (node >= N_NODES) return;

    // stage x row (128 floats) : each lane brings one float4
    const float4* xr = (const float4*)(x + (size_t)node * IN_C);
    ((float4*)sx[warp])[lane] = xr[lane];
    __syncwarp();

    float acc = 0.0f;
#pragma unroll 16
    for (int k = 0; k < IN_C; k++)
        acc = fmaf(sx[warp][k], sW[k * HID + lane], acc);  // sW: lane-stride-1, conflict-free

    g_g1[(size_t)node * HID + lane] = acc * g_dinv[node];
}

// K4: layer-1 scatter. 8 threads per edge, float4 gather + red.v4.f32 scatter.
__global__ __launch_bounds__(256) void k_scat1(const void* __restrict__ ei) {
    int t = blockIdx.x * blockDim.x + threadIdx.x;
    if (t >= N_EDGES * 8) return;
    int e = t >> 3, q = t & 7;
    int is64 = g_is64;
    int r = edge_row(ei, e, is64);
    int c = edge_col(ei, e, is64);
    const float4 v = *(const float4*)(g_g1 + (size_t)r * HID + q * 4);
    float* dst = g_acc1 + (size_t)c * HID + q * 4;
    asm volatile("red.global.add.v4.f32 [%0], {%1,%2,%3,%4};"
                 :: "l"(dst), "f"(v.x), "f"(v.y), "f"(v.z), "f"(v.w) : "memory");
}

// K5: h = relu(acc1*dinv + b1); g2 = dinv * (h @ W2). One warp per node.
__global__ __launch_bounds__(256) void k_fuse(const float* __restrict__ W2,
                                              const float* __restrict__ b1) {
    __shared__ float sW[HID * OUT_C];
    __shared__ float sb1[HID];
    __shared__ float sh[8][HID];
    for (int i = threadIdx.x; i < HID * OUT_C; i += 256) sW[i] = W2[i];
    for (int i = threadIdx.x; i < HID; i += 256) sb1[i] = b1[i];
    __syncthreads();

    int warp = threadIdx.x >> 5, lane = threadIdx.x & 31;
    int node = blockIdx.x * 8 + warp;
    if (node >= N_NODES) return;

    float dv = g_dinv[node];
    float h = fmaxf(g_acc1[(size_t)node * HID + lane] * dv + sb1[lane], 0.0f);
    sh[warp][lane] = h;
    __syncwarp();

    if (lane < OUT_C) {
        float acc = 0.0f;
#pragma unroll
        for (int k = 0; k < HID; k++)
            acc = fmaf(sh[warp][k], sW[k * OUT_C + lane], acc);
        g_g2[(size_t)node * OUT_C + lane] = acc * dv;
    }
}

// K6: layer-2 scatter. 4 threads per edge, float4 + red.v4.
__global__ __launch_bounds__(256) void k_scat2(const void* __restrict__ ei) {
    int t = blockIdx.x * blockDim.x + threadIdx.x;
    if (t >= N_EDGES * 4) return;
    int e = t >> 2, q = t & 3;
    int is64 = g_is64;
    int r = edge_row(ei, e, is64);
    int c = edge_col(ei, e, is64);
    const float4 v = *(const float4*)(g_g2 + (size_t)r * OUT_C + q * 4);
    float* dst = g_acc2 + (size_t)c * OUT_C + q * 4;
    asm volatile("red.global.add.v4.f32 [%0], {%1,%2,%3,%4};"
                 :: "l"(dst), "f"(v.x), "f"(v.y), "f"(v.z), "f"(v.w) : "memory");
}

// K7: out = acc2*dinv + b2; zero-fill any tail (tuple's scalar 0 slot).
__global__ void k_final(float* __restrict__ out, const float* __restrict__ b2,
                        int out_size) {
    int t = blockIdx.x * blockDim.x + threadIdx.x;
    if (t >= out_size) return;
    if (t < N_NODES * OUT_C) {
        int c = t / OUT_C, j = t - c * OUT_C;
        out[t] = g_acc2[t] * g_dinv[c] + b2[j];
    } else {
        out[t] = 0.0f;
    }
}

// ---------------------------------------------------------------------------
extern "C" void kernel_launch(void* const* d_in, const int* in_sizes, int n_in,
                              void* d_out, int out_size) {
    const float* x  = (const float*)d_in[0];
    const void*  ei = d_in[1];
    const float* W1 = (const float*)d_in[2];
    const float* b1 = (const float*)d_in[3];
    const float* W2 = (const float*)d_in[4];
    const float* b2 = (const float*)d_in[5];
    float* out = (float*)d_out;

    void *p_deg, *p_acc1, *p_acc2;
    cudaGetSymbolAddress(&p_deg,  g_deg);
    cudaGetSymbolAddress(&p_acc1, g_acc1);
    cudaGetSymbolAddress(&p_acc2, g_acc2);
    cudaMemsetAsync(p_deg,  0, (size_t)N_NODES * sizeof(float));
    cudaMemsetAsync(p_acc1, 0, (size_t)N_NODES * HID * sizeof(float));
    cudaMemsetAsync(p_acc2, 0, (size_t)N_NODES * OUT_C * sizeof(float));

    k_detect<<<1, 256>>>(ei);
    k_deg  <<<(N_EDGES + 255) / 256, 256>>>(ei);
    k_dinv <<<(N_NODES + 255) / 256, 256>>>();
    k_gemm1<<<(N_NODES + 7) / 8, 256>>>(x, W1);
    k_scat1<<<(N_EDGES * 8 + 255) / 256, 256>>>(ei);
    k_fuse <<<(N_NODES + 7) / 8, 256>>>(W2, b1);
    k_scat2<<<(N_EDGES * 4 + 255) / 256, 256>>>(ei);
    k_final<<<(out_size + 255) / 256, 256>>>(out, b2, out_size);
}